// round 15
// baseline (speedup 1.0000x reference)
#include <cuda_runtime.h>
#include <math.h>

#define NN 100000
#define NE 1600000
#define HH 5
#define CC 12
#define HC 60      // H*C
#define FN 128
#define FE 32

// ---------------- scratch (static device memory; no allocations) -------------
__device__ float g_q[NN * HC];
__device__ float g_k[NN * HC];
__device__ float g_v[NN * HC];
__device__ float g_skip[NN * HC];
__device__ float g_h1[NN * HC];          // layer1 output / layer2 input
__device__ float g_h2[NN * HC];          // layer2 output
__device__ float g_e[(size_t)NE * HC];   // per-edge e, in CSR order (384 MB)
__device__ int   g_off[NN + 1];
__device__ int   g_deg[NN];
__device__ int   g_fill[NN];
__device__ int   g_csr_eid[NE];
__device__ int   g_csr_src[NE];

// ---------------- CSR build --------------------------------------------------
__global__ void k_zero_deg() {
    int i = blockIdx.x * blockDim.x + threadIdx.x;
    if (i < NN) g_deg[i] = 0;
}

__global__ void k_count(const int* __restrict__ ei) {
    int i = blockIdx.x * blockDim.x + threadIdx.x;
    if (i < NE) atomicAdd(&g_deg[ei[NE + i]], 1);
}

__global__ void k_scan() {   // single block, 1024 threads
    __shared__ int part[1024];
    int t = threadIdx.x;
    const int CH = (NN + 1023) / 1024;
    int lo = t * CH;
    int hi = lo + CH; if (hi > NN) hi = NN; if (lo > NN) lo = NN;
    int s = 0;
    for (int i = lo; i < hi; ++i) s += g_deg[i];
    part[t] = s;
    __syncthreads();
    for (int off = 1; off < 1024; off <<= 1) {
        int v = (t >= off) ? part[t - off] : 0;
        __syncthreads();
        part[t] += v;
        __syncthreads();
    }
    int base = (t == 0) ? 0 : part[t - 1];
    for (int i = lo; i < hi; ++i) {
        g_off[i] = base;
        g_fill[i] = base;
        base += g_deg[i];
    }
    if (t == 1023) g_off[NN] = part[1023];
}

__global__ void k_scatter(const int* __restrict__ ei) {
    int i = blockIdx.x * blockDim.x + threadIdx.x;
    if (i >= NE) return;
    int dst = ei[NE + i];
    int src = ei[i];
    int pos = atomicAdd(&g_fill[dst], 1);
    g_csr_eid[pos] = i;
    g_csr_src[pos] = src;
}

// ---------------- node projections: q,k,v,skip = x @ W + b -------------------
// block = 240 threads, 16 nodes per block. thread t: matrix m = t/60, col c = t%60.
template <int DIN, int SRC>
__global__ void k_proj(const float* __restrict__ xin,
                       const float* __restrict__ Wq, const float* __restrict__ bq,
                       const float* __restrict__ Wk, const float* __restrict__ bk,
                       const float* __restrict__ Wv, const float* __restrict__ bv,
                       const float* __restrict__ Ws, const float* __restrict__ bs) {
    __shared__ float xs[16][DIN];
    const float* x = (SRC == 0) ? xin : (const float*)g_h1;
    const int node0 = blockIdx.x * 16;
    const int tid = threadIdx.x;

    for (int i = tid; i < 16 * DIN; i += 240) {
        int n = i / DIN, d = i - n * DIN;
        xs[n][d] = x[(size_t)(node0 + n) * DIN + d];
    }
    __syncthreads();

    const int m = tid / 60;
    const int c = tid - m * 60;
    const float* Wm = (m == 0) ? Wq : (m == 1) ? Wk : (m == 2) ? Wv : Ws;
    const float* bm = (m == 0) ? bq : (m == 1) ? bk : (m == 2) ? bv : bs;
    float* om = (m == 0) ? g_q : (m == 1) ? g_k : (m == 2) ? g_v : g_skip;

    float acc[16];
#pragma unroll
    for (int n = 0; n < 16; ++n) acc[n] = 0.f;

#pragma unroll 2
    for (int d = 0; d < DIN; d += 4) {
        float w0 = Wm[(d + 0) * 60 + c];
        float w1 = Wm[(d + 1) * 60 + c];
        float w2 = Wm[(d + 2) * 60 + c];
        float w3 = Wm[(d + 3) * 60 + c];
#pragma unroll
        for (int n = 0; n < 16; ++n) {
            float4 xv = *(const float4*)&xs[n][d];
            acc[n] = fmaf(xv.x, w0, acc[n]);
            acc[n] = fmaf(xv.y, w1, acc[n]);
            acc[n] = fmaf(xv.z, w2, acc[n]);
            acc[n] = fmaf(xv.w, w3, acc[n]);
        }
    }
    float bias = bm[c];
#pragma unroll
    for (int n = 0; n < 16; ++n)
        om[(size_t)(node0 + n) * 60 + c] = acc[n] + bias;
}

// ---------------- per-edge e = edge_attr @ We (written in CSR order) ---------
__global__ void k_edge_e(const float* __restrict__ edge_attr, const float* __restrict__ We) {
    __shared__ float ws[FE * HC];   // 1920 floats
    const int tid = threadIdx.x;
    for (int i = tid; i < FE * HC; i += blockDim.x) ws[i] = We[i];
    __syncthreads();

    const int i = blockIdx.x * blockDim.x + tid;    // csr position (grid exact)
    const int eid = g_csr_eid[i];
    const float4* ap = (const float4*)(edge_attr + (size_t)eid * FE);

    float a[FE];
#pragma unroll
    for (int j = 0; j < FE / 4; ++j) {
        float4 v = ap[j];
        a[4 * j + 0] = v.x; a[4 * j + 1] = v.y; a[4 * j + 2] = v.z; a[4 * j + 3] = v.w;
    }

    float4 acc[15];
#pragma unroll
    for (int j = 0; j < 15; ++j) acc[j] = make_float4(0.f, 0.f, 0.f, 0.f);

    const float4* ws4 = (const float4*)ws;
#pragma unroll
    for (int d = 0; d < FE; ++d) {
        float av = a[d];
#pragma unroll
        for (int j = 0; j < 15; ++j) {
            float4 w = ws4[d * 15 + j];
            acc[j].x = fmaf(av, w.x, acc[j].x);
            acc[j].y = fmaf(av, w.y, acc[j].y);
            acc[j].z = fmaf(av, w.z, acc[j].z);
            acc[j].w = fmaf(av, w.w, acc[j].w);
        }
    }
    float4* op = (float4*)(g_e + (size_t)i * HC);
#pragma unroll
    for (int j = 0; j < 15; ++j) op[j] = acc[j];
}

// ---------------- per-dst online-softmax attention + skip + ReLU -------------
// one thread per (node, head); 5 consecutive threads cover one node's 60 floats.
template <int LAYER>
__global__ void k_attn() {
    const int t = blockIdx.x * blockDim.x + threadIdx.x;
    if (t >= NN * HH) return;
    const int node = t / HH;
    const int h = t - node * HH;
    const int base = node * HC + h * CC;

    const float4 q0 = *(const float4*)(g_q + base);
    const float4 q1 = *(const float4*)(g_q + base + 4);
    const float4 q2 = *(const float4*)(g_q + base + 8);

    float m = -3.0e38f, s = 0.f;
    float acc[CC];
#pragma unroll
    for (int c = 0; c < CC; ++c) acc[c] = 0.f;

    const int beg = g_off[node];
    const int end = g_off[node + 1];
    const float scale = 0.28867513459481287f;   // 1/sqrt(12)

    for (int i = beg; i < end; ++i) {
        const int src = g_csr_src[i];
        const float* ep = g_e + (size_t)i * HC + h * CC;
        const float* kp = g_k + (size_t)src * HC + h * CC;
        const float4 e0 = *(const float4*)(ep);
        const float4 e1 = *(const float4*)(ep + 4);
        const float4 e2 = *(const float4*)(ep + 8);
        const float4 k0 = *(const float4*)(kp);
        const float4 k1 = *(const float4*)(kp + 4);
        const float4 k2 = *(const float4*)(kp + 8);

        float a = q0.x * (k0.x + e0.x) + q0.y * (k0.y + e0.y) +
                  q0.z * (k0.z + e0.z) + q0.w * (k0.w + e0.w) +
                  q1.x * (k1.x + e1.x) + q1.y * (k1.y + e1.y) +
                  q1.z * (k1.z + e1.z) + q1.w * (k1.w + e1.w) +
                  q2.x * (k2.x + e2.x) + q2.y * (k2.y + e2.y) +
                  q2.z * (k2.z + e2.z) + q2.w * (k2.w + e2.w);
        a *= scale;

        float w;
        if (a > m) {
            float sc = expf(m - a);   // 0 on first edge (m = -3e38)
            s *= sc;
#pragma unroll
            for (int c = 0; c < CC; ++c) acc[c] *= sc;
            m = a;
            w = 1.0f;
        } else {
            w = expf(a - m);
        }
        s += w;

        const float* vp = g_v + (size_t)src * HC + h * CC;
        const float4 v0 = *(const float4*)(vp);
        const float4 v1 = *(const float4*)(vp + 4);
        const float4 v2 = *(const float4*)(vp + 8);
        acc[0] = fmaf(w, v0.x + e0.x, acc[0]);
        acc[1] = fmaf(w, v0.y + e0.y, acc[1]);
        acc[2] = fmaf(w, v0.z + e0.z, acc[2]);
        acc[3] = fmaf(w, v0.w + e0.w, acc[3]);
        acc[4] = fmaf(w, v1.x + e1.x, acc[4]);
        acc[5] = fmaf(w, v1.y + e1.y, acc[5]);
        acc[6] = fmaf(w, v1.z + e1.z, acc[6]);
        acc[7] = fmaf(w, v1.w + e1.w, acc[7]);
        acc[8] = fmaf(w, v2.x + e2.x, acc[8]);
        acc[9] = fmaf(w, v2.y + e2.y, acc[9]);
        acc[10] = fmaf(w, v2.z + e2.z, acc[10]);
        acc[11] = fmaf(w, v2.w + e2.w, acc[11]);
    }

    const float inv = 1.0f / (s + 1e-16f);
    float* op = ((LAYER == 1) ? g_h1 : g_h2) + base;
    const float* sp = g_skip + base;
#pragma unroll
    for (int c = 0; c < CC; ++c) {
        float o = fmaf(acc[c], inv, sp[c]);
        op[c] = fmaxf(o, 0.f);
    }
}

// ---------------- final MLP: relu(h@W1+b1)@W2+b2 -----------------------------
__global__ void k_mlp(const float* __restrict__ W1, const float* __restrict__ b1,
                      const float* __restrict__ W2, const float* __restrict__ b2,
                      float* __restrict__ out) {
    __shared__ float ws1[HC * 16];
    __shared__ float b1s[16];
    __shared__ float ws2[32];
    __shared__ float b2s[2];
    __shared__ float hs[128 * HC];
    const int tid = threadIdx.x;
    for (int i = tid; i < HC * 16; i += blockDim.x) ws1[i] = W1[i];
    if (tid < 16) b1s[tid] = b1[tid];
    if (tid < 32) ws2[tid] = W2[tid];
    if (tid < 2)  b2s[tid] = b2[tid];

    const size_t gbase = (size_t)blockIdx.x * 128 * HC;
    for (int i = tid; i < 128 * HC; i += blockDim.x) {
        size_t g = gbase + i;
        hs[i] = (g < (size_t)NN * HC) ? g_h2[g] : 0.f;
    }
    __syncthreads();

    const int n = blockIdx.x * 128 + tid;
    if (n >= NN) return;

    float hid[16];
#pragma unroll
    for (int j = 0; j < 16; ++j) hid[j] = b1s[j];
    const float* hp = hs + tid * HC;
#pragma unroll 4
    for (int d = 0; d < HC; ++d) {
        float hv = hp[d];
#pragma unroll
        for (int j = 0; j < 16; ++j) hid[j] = fmaf(hv, ws1[d * 16 + j], hid[j]);
    }
    float o0 = b2s[0], o1 = b2s[1];
#pragma unroll
    for (int j = 0; j < 16; ++j) {
        float hv = fmaxf(hid[j], 0.f);
        o0 = fmaf(hv, ws2[j * 2 + 0], o0);
        o1 = fmaf(hv, ws2[j * 2 + 1], o1);
    }
    out[n * 2 + 0] = o0;
    out[n * 2 + 1] = o1;
}

// ---------------- launch -----------------------------------------------------
extern "C" void kernel_launch(void* const* d_in, const int* in_sizes, int n_in,
                              void* d_out, int out_size) {
    const float* x   = (const float*)d_in[0];
    const int*   ei  = (const int*)d_in[1];
    const float* ea  = (const float*)d_in[2];
    const float* Wq1 = (const float*)d_in[3];
    const float* bq1 = (const float*)d_in[4];
    const float* Wk1 = (const float*)d_in[5];
    const float* bk1 = (const float*)d_in[6];
    const float* Wv1 = (const float*)d_in[7];
    const float* bv1 = (const float*)d_in[8];
    const float* We1 = (const float*)d_in[9];
    const float* Ws1 = (const float*)d_in[10];
    const float* bs1 = (const float*)d_in[11];
    const float* Wq2 = (const float*)d_in[12];
    const float* bq2 = (const float*)d_in[13];
    const float* Wk2 = (const float*)d_in[14];
    const float* bk2 = (const float*)d_in[15];
    const float* Wv2 = (const float*)d_in[16];
    const float* bv2 = (const float*)d_in[17];
    const float* We2 = (const float*)d_in[18];
    const float* Ws2 = (const float*)d_in[19];
    const float* bs2 = (const float*)d_in[20];
    const float* W1  = (const float*)d_in[21];
    const float* b1  = (const float*)d_in[22];
    const float* W2  = (const float*)d_in[23];
    const float* b2  = (const float*)d_in[24];
    float* out = (float*)d_out;

    // CSR build (recomputed every call; deterministic workload)
    k_zero_deg<<<(NN + 255) / 256, 256>>>();
    k_count<<<(NE + 255) / 256, 256>>>(ei);
    k_scan<<<1, 1024>>>();
    k_scatter<<<(NE + 255) / 256, 256>>>(ei);

    // layer 1
    k_proj<FN, 0><<<NN / 16, 240>>>(x, Wq1, bq1, Wk1, bk1, Wv1, bv1, Ws1, bs1);
    k_edge_e<<<NE / 128, 128>>>(ea, We1);
    k_attn<1><<<(NN * HH + 319) / 320, 320>>>();

    // layer 2 (input g_h1)
    k_proj<HC, 1><<<NN / 16, 240>>>(x, Wq2, bq2, Wk2, bk2, Wv2, bv2, Ws2, bs2);
    k_edge_e<<<NE / 128, 128>>>(ea, We2);
    k_attn<2><<<(NN * HH + 319) / 320, 320>>>();

    // MLP head
    k_mlp<<<(NN + 127) / 128, 128>>>(W1, b1, W2, b2, out);
}